// round 8
// baseline (speedup 1.0000x reference)
#include <cuda_runtime.h>
#include <cstdint>

// MMD loss via tf32 mma.sync GEMM (compute_103-safe; no tcgen05).
//   Z -> tf32-rounded copy g_ztf (cvt.rna). dot via m16n8k8 tf32 MMA, fp32 accum.
//   d2 = s_i + s_j - 2 dot ; bw analytic ; K = 5-kernel sum via ex2 + squarings.
//   Triangular tile launch (2080 CTAs x 256 thr), 128x128 tile, BK=32, K=256.
//   cp.async double-buffered smem, 2 CTAs/SM.

#define N_HALF 4096
#define N_TOT  8192
#define DIM    256
#define BM     128
#define BK     32
#define TILES  64
#define HALF_TILES 32
#define NPAIRS 2080
#define LDA    36            // padded smem row stride in floats (bank-conflict-free)

// dynamic smem float offsets
#define OFF_A0 0
#define OFF_A1 4608
#define OFF_B0 9216
#define OFF_B1 13824
#define OFF_SA 18432
#define OFF_SBN 18560
#define OFF_RED 18688        // byte 74752, 8-aligned
#define SMEM_BYTES (74752 + 64)

__device__ float  g_ztf[(size_t)N_TOT * DIM];
__device__ float  g_snorm[N_TOT];
__device__ double g_colpart[256 * 256];
__device__ float  g_coef;             // log2(e)/(4*bw)
__device__ double g_part[NPAIRS];

__device__ __forceinline__ const float* zptr(const float* X, const float* Y, int r) {
    return (r < N_HALF) ? (X + (size_t)r * DIM) : (Y + (size_t)(r - N_HALF) * DIM);
}

__device__ __forceinline__ float ex2f(float x) {
    float y; asm("ex2.approx.ftz.f32 %0, %1;" : "=f"(y) : "f"(x)); return y;
}

__device__ __forceinline__ uint32_t smem_u32(const void* p) {
    uint32_t a;
    asm("{ .reg .u64 t; cvta.to.shared.u64 t, %1; cvt.u32.u64 %0, t; }" : "=r"(a) : "l"(p));
    return a;
}

__device__ __forceinline__ void cp16(uint32_t dst, const void* src) {
    asm volatile("cp.async.cg.shared.global [%0], [%1], 16;" :: "r"(dst), "l"(src));
}

__device__ __forceinline__ void mma_tf32(float* c, uint32_t a0, uint32_t a1,
                                         uint32_t a2, uint32_t a3,
                                         uint32_t b0, uint32_t b1) {
    asm volatile(
        "mma.sync.aligned.m16n8k8.row.col.f32.tf32.tf32.f32 "
        "{%0,%1,%2,%3}, {%4,%5,%6,%7}, {%8,%9}, {%0,%1,%2,%3};"
        : "+f"(c[0]), "+f"(c[1]), "+f"(c[2]), "+f"(c[3])
        : "r"(a0), "r"(a1), "r"(a2), "r"(a3), "r"(b0), "r"(b1));
}

// ---------------------------------------------------------------------------
// Pre-pass: tf32-rounded copy + column partial sums + row squared norms.
// ---------------------------------------------------------------------------
__global__ void __launch_bounds__(256) k_pre(const float* __restrict__ X,
                                             const float* __restrict__ Y) {
    int t = threadIdx.x;
    int r0 = blockIdx.x * 32;

    double acc = 0.0;
    #pragma unroll 4
    for (int r = 0; r < 32; r++) {
        int row = r0 + r;
        float v = zptr(X, Y, row)[t];
        acc += (double)v;
        uint32_t tf;
        asm("cvt.rna.tf32.f32 %0, %1;" : "=r"(tf) : "f"(v));
        g_ztf[(size_t)row * DIM + t] = __uint_as_float(tf);
    }
    g_colpart[blockIdx.x * 256 + t] = acc;

    int warp = t >> 5, lane = t & 31;
    #pragma unroll
    for (int rr = 0; rr < 4; rr++) {
        int row = r0 + warp * 4 + rr;
        const float* zr = zptr(X, Y, row);
        float s = 0.f;
        #pragma unroll
        for (int c = lane; c < DIM; c += 32) { float v = zr[c]; s = fmaf(v, v, s); }
        #pragma unroll
        for (int o = 16; o; o >>= 1) s += __shfl_xor_sync(0xffffffffu, s, o);
        if (lane == 0) g_snorm[row] = s;
    }
}

// ---------------------------------------------------------------------------
// Bandwidth -> exponent coefficient. Single block, deterministic.
// ---------------------------------------------------------------------------
__global__ void __launch_bounds__(256) k_bw() {
    __shared__ double sh[256];
    int t = threadIdx.x;
    double ss = 0.0;
    for (int i = t; i < N_TOT; i += 256) ss += (double)g_snorm[i];
    sh[t] = ss; __syncthreads();
    for (int o = 128; o; o >>= 1) { if (t < o) sh[t] += sh[t + o]; __syncthreads(); }
    double sum_s = sh[0];
    __syncthreads();
    double C = 0.0;
    for (int b = 0; b < 256; b++) C += g_colpart[b * 256 + t];
    sh[t] = C * C; __syncthreads();
    for (int o = 128; o; o >>= 1) { if (t < o) sh[t] += sh[t + o]; __syncthreads(); }
    if (t == 0) {
        double total = 2.0 * (double)N_TOT * sum_s - 2.0 * sh[0];
        double bw = total / ((double)N_TOT * (double)N_TOT - (double)N_TOT);
        g_coef = (float)(1.4426950408889634 / (4.0 * bw));
    }
}

// ---------------------------------------------------------------------------
// Main: one 128x128 tile-pair per CTA; tf32 mma.sync; cp.async pipeline.
// 8 warps as 2(m) x 4(n); each warp: 64x32 region = 4x4 m16n8 tiles.
// ---------------------------------------------------------------------------
__global__ void __launch_bounds__(256, 2) k_main() {
    extern __shared__ float sm[];
    float* sA  = sm + OFF_SA;
    float* sBn = sm + OFF_SBN;
    double* red = (double*)(sm + OFF_RED);

    int tid = threadIdx.x, lane = tid & 31, wid = tid >> 5;

    // decode linear id -> (ti, tj), ti <= tj
    int L = blockIdx.x;
    int ti = (int)((129.0 - sqrt(16641.0 - 8.0 * (double)L)) * 0.5);
    if (ti > TILES - 1) ti = TILES - 1;
    if (ti < 0) ti = 0;
    while ((ti + 1) * (129 - (ti + 1)) / 2 <= L) ti++;
    while (ti * (129 - ti) / 2 > L) ti--;
    int tj = ti + (L - ti * (129 - ti) / 2);

    const float* Ag = g_ztf + (size_t)ti * BM * DIM;
    const float* Bg = g_ztf + (size_t)tj * BM * DIM;

    if (tid < 128) sA[tid] = g_snorm[ti * BM + tid];
    else           sBn[tid - 128] = g_snorm[tj * BM + tid - 128];

    // per-thread cp.async source/dest (4 x 16B chunks per matrix per buffer)
    int idx0 = tid;                 // q*256 + tid, q=0..3
    uint32_t smA[2] = { smem_u32(sm + OFF_A0), smem_u32(sm + OFF_A1) };
    uint32_t smB[2] = { smem_u32(sm + OFF_B0), smem_u32(sm + OFF_B1) };

    #define ISSUE(buf, k0)                                                     \
        {                                                                      \
            _Pragma("unroll")                                                  \
            for (int q = 0; q < 4; q++) {                                      \
                int idx = q * 256 + idx0;                                      \
                int row = idx >> 3, c4 = (idx & 7) * 4;                        \
                uint32_t doff = (uint32_t)(row * LDA + c4) * 4u;               \
                cp16(smA[buf] + doff, Ag + (size_t)row * DIM + (k0) + c4);     \
                cp16(smB[buf] + doff, Bg + (size_t)row * DIM + (k0) + c4);     \
            }                                                                  \
            asm volatile("cp.async.commit_group;" ::: "memory");               \
        }

    ISSUE(0, 0)

    float acc[16][4];
    #pragma unroll
    for (int i = 0; i < 16; i++)
        #pragma unroll
        for (int j = 0; j < 4; j++) acc[i][j] = 0.f;

    int wm = wid >> 2, wn = wid & 3;
    int g = lane >> 2, cq = lane & 3;
    int aoff = (wm * 64 + g) * LDA + cq;
    int boff = (wn * 32 + g) * LDA + cq;

    const int NIT = DIM / BK;   // 8
    for (int it = 0; it < NIT; it++) {
        int cur = it & 1;
        bool more = (it + 1 < NIT);
        if (more) ISSUE(cur ^ 1, (it + 1) * BK)

        if (more) asm volatile("cp.async.wait_group 1;" ::: "memory");
        else      asm volatile("cp.async.wait_group 0;" ::: "memory");
        __syncthreads();

        const float* Ac = sm + (cur ? OFF_A1 : OFF_A0);
        const float* Bc = sm + (cur ? OFF_B1 : OFF_B0);
        #pragma unroll
        for (int ks = 0; ks < 4; ks++) {
            int kc = ks * 8;
            uint32_t bf[4][2];
            #pragma unroll
            for (int nt = 0; nt < 4; nt++) {
                bf[nt][0] = __float_as_uint(Bc[boff + nt * 8 * LDA + kc]);
                bf[nt][1] = __float_as_uint(Bc[boff + nt * 8 * LDA + kc + 4]);
            }
            #pragma unroll
            for (int mt = 0; mt < 4; mt++) {
                uint32_t a0 = __float_as_uint(Ac[aoff + (mt * 16)     * LDA + kc]);
                uint32_t a1 = __float_as_uint(Ac[aoff + (mt * 16 + 8) * LDA + kc]);
                uint32_t a2 = __float_as_uint(Ac[aoff + (mt * 16)     * LDA + kc + 4]);
                uint32_t a3 = __float_as_uint(Ac[aoff + (mt * 16 + 8) * LDA + kc + 4]);
                #pragma unroll
                for (int nt = 0; nt < 4; nt++)
                    mma_tf32(acc[mt * 4 + nt], a0, a1, a2, a3, bf[nt][0], bf[nt][1]);
            }
        }
        __syncthreads();
    }

    // Epilogue on register fragments.
    float c = g_coef;
    float twoC = 2.f * c;
    float rA[8], cB[8];
    #pragma unroll
    for (int mt = 0; mt < 4; mt++) {
        rA[mt * 2 + 0] = sA[wm * 64 + mt * 16 + g]     * c;
        rA[mt * 2 + 1] = sA[wm * 64 + mt * 16 + g + 8] * c;
    }
    #pragma unroll
    for (int nt = 0; nt < 4; nt++) {
        cB[nt * 2 + 0] = sBn[wn * 32 + nt * 8 + cq * 2]     * c;
        cB[nt * 2 + 1] = sBn[wn * 32 + nt * 8 + cq * 2 + 1] * c;
    }

    float psum = 0.f;
    #pragma unroll
    for (int mt = 0; mt < 4; mt++) {
        #pragma unroll
        for (int nt = 0; nt < 4; nt++) {
            float* cc = acc[mt * 4 + nt];
            #pragma unroll
            for (int u = 0; u < 4; u++) {
                int h = u >> 1, e = u & 1;
                float arg = fmaf(cc[u], twoC, -(rA[mt * 2 + h] + cB[nt * 2 + e]));
                arg = fminf(arg, 0.f);           // d2 clamp
                float ee = ex2f(arg);            // mult 4
                float t2 = ee * ee;              // mult 2
                float ks = ee + t2;
                float t4 = t2 * t2;  ks += t4;   // mult 1
                float t8 = t4 * t4;  ks += t8;   // mult 1/2
                ks = fmaf(t8, t8, ks);           // mult 1/4
                psum += ks;
            }
        }
    }

    double wsum = (double)psum;
    #pragma unroll
    for (int o = 16; o; o >>= 1) wsum += __shfl_xor_sync(0xffffffffu, wsum, o);
    if (lane == 0) red[wid] = wsum;
    __syncthreads();
    if (tid == 0) {
        double s = 0.0;
        #pragma unroll
        for (int w = 0; w < 8; w++) s += red[w];
        double wgt = ((ti < HALF_TILES) == (tj < HALF_TILES)) ? 1.0 : -1.0;
        if (ti != tj) wgt *= 2.0;
        g_part[L] = s * wgt;
    }
}

// ---------------------------------------------------------------------------
// Final deterministic reduction + scale.
// ---------------------------------------------------------------------------
__global__ void __launch_bounds__(256) k_final(float* __restrict__ out) {
    __shared__ double sh[256];
    int t = threadIdx.x;
    double a = 0.0;
    for (int i = t; i < NPAIRS; i += 256) a += g_part[i];
    sh[t] = a; __syncthreads();
    for (int o = 128; o; o >>= 1) { if (t < o) sh[t] += sh[t + o]; __syncthreads(); }
    if (t == 0)
        out[0] = (float)(sh[0] / ((double)N_HALF * (double)N_HALF));
}

extern "C" void kernel_launch(void* const* d_in, const int* in_sizes, int n_in,
                              void* d_out, int out_size) {
    const float* X = (const float*)d_in[0];
    const float* Y = (const float*)d_in[1];
    float* out = (float*)d_out;
    (void)in_sizes; (void)n_in; (void)out_size;

    cudaFuncSetAttribute(k_main, cudaFuncAttributeMaxDynamicSharedMemorySize, SMEM_BYTES);

    k_pre<<<256, 256>>>(X, Y);
    k_bw<<<1, 256>>>();
    k_main<<<NPAIRS, 256, SMEM_BYTES>>>();
    k_final<<<1, 256>>>(out);
}

// round 9
// speedup vs baseline: 1.0063x; 1.0063x over previous
#include <cuda_runtime.h>
#include <cstdint>

// MMD loss via tf32 mma.sync GEMM (compute_103-safe; no tcgen05).
//   Z -> tf32-rounded copy g_ztf (cvt.rna). dot via m16n8k8 tf32 MMA, fp32 accum.
//   d2 = s_i + s_j - 2 dot ; bw analytic ; K = 5-kernel sum via ex2 + squarings.
//   Triangular tile launch (2080 CTAs x 256 thr), 128x128 tile, BK=32, K=256.
//   cp.async double-buffered smem, 2 CTAs/SM.

#define N_HALF 4096
#define N_TOT  8192
#define DIM    256
#define BM     128
#define BK     32
#define TILES  64
#define HALF_TILES 32
#define NPAIRS 2080
#define LDA    36            // padded smem row stride in floats (bank-conflict-free)

// dynamic smem float offsets
#define OFF_A0 0
#define OFF_A1 4608
#define OFF_B0 9216
#define OFF_B1 13824
#define OFF_SA 18432
#define OFF_SBN 18560
#define OFF_RED 18688        // byte 74752, 8-aligned
#define SMEM_BYTES (74752 + 64)

__device__ float  g_ztf[(size_t)N_TOT * DIM];
__device__ float  g_snorm[N_TOT];
__device__ double g_colpart[256 * 256];
__device__ float  g_coef;             // log2(e)/(4*bw)
__device__ double g_part[NPAIRS];

__device__ __forceinline__ const float* zptr(const float* X, const float* Y, int r) {
    return (r < N_HALF) ? (X + (size_t)r * DIM) : (Y + (size_t)(r - N_HALF) * DIM);
}

__device__ __forceinline__ float ex2f(float x) {
    float y; asm("ex2.approx.ftz.f32 %0, %1;" : "=f"(y) : "f"(x)); return y;
}

__device__ __forceinline__ uint32_t smem_u32(const void* p) {
    uint32_t a;
    asm("{ .reg .u64 t; cvta.to.shared.u64 t, %1; cvt.u32.u64 %0, t; }" : "=r"(a) : "l"(p));
    return a;
}

__device__ __forceinline__ void cp16(uint32_t dst, const void* src) {
    asm volatile("cp.async.cg.shared.global [%0], [%1], 16;" :: "r"(dst), "l"(src));
}

__device__ __forceinline__ void mma_tf32(float* c, uint32_t a0, uint32_t a1,
                                         uint32_t a2, uint32_t a3,
                                         uint32_t b0, uint32_t b1) {
    asm volatile(
        "mma.sync.aligned.m16n8k8.row.col.f32.tf32.tf32.f32 "
        "{%0,%1,%2,%3}, {%4,%5,%6,%7}, {%8,%9}, {%0,%1,%2,%3};"
        : "+f"(c[0]), "+f"(c[1]), "+f"(c[2]), "+f"(c[3])
        : "r"(a0), "r"(a1), "r"(a2), "r"(a3), "r"(b0), "r"(b1));
}

// ---------------------------------------------------------------------------
// Pre-pass: tf32-rounded copy + column partial sums + row squared norms.
// ---------------------------------------------------------------------------
__global__ void __launch_bounds__(256) k_pre(const float* __restrict__ X,
                                             const float* __restrict__ Y) {
    int t = threadIdx.x;
    int r0 = blockIdx.x * 32;

    double acc = 0.0;
    #pragma unroll 4
    for (int r = 0; r < 32; r++) {
        int row = r0 + r;
        float v = zptr(X, Y, row)[t];
        acc += (double)v;
        uint32_t tf;
        asm("cvt.rna.tf32.f32 %0, %1;" : "=r"(tf) : "f"(v));
        g_ztf[(size_t)row * DIM + t] = __uint_as_float(tf);
    }
    g_colpart[blockIdx.x * 256 + t] = acc;

    int warp = t >> 5, lane = t & 31;
    #pragma unroll
    for (int rr = 0; rr < 4; rr++) {
        int row = r0 + warp * 4 + rr;
        const float* zr = zptr(X, Y, row);
        float s = 0.f;
        #pragma unroll
        for (int c = lane; c < DIM; c += 32) { float v = zr[c]; s = fmaf(v, v, s); }
        #pragma unroll
        for (int o = 16; o; o >>= 1) s += __shfl_xor_sync(0xffffffffu, s, o);
        if (lane == 0) g_snorm[row] = s;
    }
}

// ---------------------------------------------------------------------------
// Bandwidth -> exponent coefficient. Single block, deterministic.
// ---------------------------------------------------------------------------
__global__ void __launch_bounds__(256) k_bw() {
    __shared__ double sh[256];
    int t = threadIdx.x;
    double ss = 0.0;
    for (int i = t; i < N_TOT; i += 256) ss += (double)g_snorm[i];
    sh[t] = ss; __syncthreads();
    for (int o = 128; o; o >>= 1) { if (t < o) sh[t] += sh[t + o]; __syncthreads(); }
    double sum_s = sh[0];
    __syncthreads();
    double C = 0.0;
    for (int b = 0; b < 256; b++) C += g_colpart[b * 256 + t];
    sh[t] = C * C; __syncthreads();
    for (int o = 128; o; o >>= 1) { if (t < o) sh[t] += sh[t + o]; __syncthreads(); }
    if (t == 0) {
        double total = 2.0 * (double)N_TOT * sum_s - 2.0 * sh[0];
        double bw = total / ((double)N_TOT * (double)N_TOT - (double)N_TOT);
        g_coef = (float)(1.4426950408889634 / (4.0 * bw));
    }
}

// ---------------------------------------------------------------------------
// Main: one 128x128 tile-pair per CTA; tf32 mma.sync; cp.async pipeline.
// 8 warps as 2(m) x 4(n); each warp: 64x32 region = 4x4 m16n8 tiles.
// ---------------------------------------------------------------------------
__global__ void __launch_bounds__(256, 2) k_main() {
    extern __shared__ float sm[];
    float* sA  = sm + OFF_SA;
    float* sBn = sm + OFF_SBN;
    double* red = (double*)(sm + OFF_RED);

    int tid = threadIdx.x, lane = tid & 31, wid = tid >> 5;

    // decode linear id -> (ti, tj), ti <= tj
    int L = blockIdx.x;
    int ti = (int)((129.0 - sqrt(16641.0 - 8.0 * (double)L)) * 0.5);
    if (ti > TILES - 1) ti = TILES - 1;
    if (ti < 0) ti = 0;
    while ((ti + 1) * (129 - (ti + 1)) / 2 <= L) ti++;
    while (ti * (129 - ti) / 2 > L) ti--;
    int tj = ti + (L - ti * (129 - ti) / 2);

    const float* Ag = g_ztf + (size_t)ti * BM * DIM;
    const float* Bg = g_ztf + (size_t)tj * BM * DIM;

    if (tid < 128) sA[tid] = g_snorm[ti * BM + tid];
    else           sBn[tid - 128] = g_snorm[tj * BM + tid - 128];

    // per-thread cp.async source/dest (4 x 16B chunks per matrix per buffer)
    int idx0 = tid;                 // q*256 + tid, q=0..3
    uint32_t smA[2] = { smem_u32(sm + OFF_A0), smem_u32(sm + OFF_A1) };
    uint32_t smB[2] = { smem_u32(sm + OFF_B0), smem_u32(sm + OFF_B1) };

    #define ISSUE(buf, k0)                                                     \
        {                                                                      \
            _Pragma("unroll")                                                  \
            for (int q = 0; q < 4; q++) {                                      \
                int idx = q * 256 + idx0;                                      \
                int row = idx >> 3, c4 = (idx & 7) * 4;                        \
                uint32_t doff = (uint32_t)(row * LDA + c4) * 4u;               \
                cp16(smA[buf] + doff, Ag + (size_t)row * DIM + (k0) + c4);     \
                cp16(smB[buf] + doff, Bg + (size_t)row * DIM + (k0) + c4);     \
            }                                                                  \
            asm volatile("cp.async.commit_group;" ::: "memory");               \
        }

    ISSUE(0, 0)

    float acc[16][4];
    #pragma unroll
    for (int i = 0; i < 16; i++)
        #pragma unroll
        for (int j = 0; j < 4; j++) acc[i][j] = 0.f;

    int wm = wid >> 2, wn = wid & 3;
    int g = lane >> 2, cq = lane & 3;
    int aoff = (wm * 64 + g) * LDA + cq;
    int boff = (wn * 32 + g) * LDA + cq;

    const int NIT = DIM / BK;   // 8
    for (int it = 0; it < NIT; it++) {
        int cur = it & 1;
        bool more = (it + 1 < NIT);
        if (more) ISSUE(cur ^ 1, (it + 1) * BK)

        if (more) asm volatile("cp.async.wait_group 1;" ::: "memory");
        else      asm volatile("cp.async.wait_group 0;" ::: "memory");
        __syncthreads();

        const float* Ac = sm + (cur ? OFF_A1 : OFF_A0);
        const float* Bc = sm + (cur ? OFF_B1 : OFF_B0);
        #pragma unroll
        for (int ks = 0; ks < 4; ks++) {
            int kc = ks * 8;
            uint32_t bf[4][2];
            #pragma unroll
            for (int nt = 0; nt < 4; nt++) {
                bf[nt][0] = __float_as_uint(Bc[boff + nt * 8 * LDA + kc]);
                bf[nt][1] = __float_as_uint(Bc[boff + nt * 8 * LDA + kc + 4]);
            }
            #pragma unroll
            for (int mt = 0; mt < 4; mt++) {
                uint32_t a0 = __float_as_uint(Ac[aoff + (mt * 16)     * LDA + kc]);
                uint32_t a1 = __float_as_uint(Ac[aoff + (mt * 16 + 8) * LDA + kc]);
                uint32_t a2 = __float_as_uint(Ac[aoff + (mt * 16)     * LDA + kc + 4]);
                uint32_t a3 = __float_as_uint(Ac[aoff + (mt * 16 + 8) * LDA + kc + 4]);
                #pragma unroll
                for (int nt = 0; nt < 4; nt++)
                    mma_tf32(acc[mt * 4 + nt], a0, a1, a2, a3, bf[nt][0], bf[nt][1]);
            }
        }
        __syncthreads();
    }

    // Epilogue on register fragments.
    float c = g_coef;
    float twoC = 2.f * c;
    float rA[8], cB[8];
    #pragma unroll
    for (int mt = 0; mt < 4; mt++) {
        rA[mt * 2 + 0] = sA[wm * 64 + mt * 16 + g]     * c;
        rA[mt * 2 + 1] = sA[wm * 64 + mt * 16 + g + 8] * c;
    }
    #pragma unroll
    for (int nt = 0; nt < 4; nt++) {
        cB[nt * 2 + 0] = sBn[wn * 32 + nt * 8 + cq * 2]     * c;
        cB[nt * 2 + 1] = sBn[wn * 32 + nt * 8 + cq * 2 + 1] * c;
    }

    float psum = 0.f;
    #pragma unroll
    for (int mt = 0; mt < 4; mt++) {
        #pragma unroll
        for (int nt = 0; nt < 4; nt++) {
            float* cc = acc[mt * 4 + nt];
            #pragma unroll
            for (int u = 0; u < 4; u++) {
                int h = u >> 1, e = u & 1;
                float arg = fmaf(cc[u], twoC, -(rA[mt * 2 + h] + cB[nt * 2 + e]));
                arg = fminf(arg, 0.f);           // d2 clamp
                float ee = ex2f(arg);            // mult 4
                float t2 = ee * ee;              // mult 2
                float ks = ee + t2;
                float t4 = t2 * t2;  ks += t4;   // mult 1
                float t8 = t4 * t4;  ks += t8;   // mult 1/2
                ks = fmaf(t8, t8, ks);           // mult 1/4
                psum += ks;
            }
        }
    }

    double wsum = (double)psum;
    #pragma unroll
    for (int o = 16; o; o >>= 1) wsum += __shfl_xor_sync(0xffffffffu, wsum, o);
    if (lane == 0) red[wid] = wsum;
    __syncthreads();
    if (tid == 0) {
        double s = 0.0;
        #pragma unroll
        for (int w = 0; w < 8; w++) s += red[w];
        double wgt = ((ti < HALF_TILES) == (tj < HALF_TILES)) ? 1.0 : -1.0;
        if (ti != tj) wgt *= 2.0;
        g_part[L] = s * wgt;
    }
}

// ---------------------------------------------------------------------------
// Final deterministic reduction + scale.
// ---------------------------------------------------------------------------
__global__ void __launch_bounds__(256) k_final(float* __restrict__ out) {
    __shared__ double sh[256];
    int t = threadIdx.x;
    double a = 0.0;
    for (int i = t; i < NPAIRS; i += 256) a += g_part[i];
    sh[t] = a; __syncthreads();
    for (int o = 128; o; o >>= 1) { if (t < o) sh[t] += sh[t + o]; __syncthreads(); }
    if (t == 0)
        out[0] = (float)(sh[0] / ((double)N_HALF * (double)N_HALF));
}

extern "C" void kernel_launch(void* const* d_in, const int* in_sizes, int n_in,
                              void* d_out, int out_size) {
    const float* X = (const float*)d_in[0];
    const float* Y = (const float*)d_in[1];
    float* out = (float*)d_out;
    (void)in_sizes; (void)n_in; (void)out_size;

    cudaFuncSetAttribute(k_main, cudaFuncAttributeMaxDynamicSharedMemorySize, SMEM_BYTES);

    k_pre<<<256, 256>>>(X, Y);
    k_bw<<<1, 256>>>();
    k_main<<<NPAIRS, 256, SMEM_BYTES>>>();
    k_final<<<1, 256>>>(out);
}